// round 1
// baseline (speedup 1.0000x reference)
#include <cuda_runtime.h>
#include <math.h>

#define NN 2048
#define BB 32
#define NSTEPS 10
#define JS 8
#define JCH (NN / JS)      // 256
#define ITILE 128
#define DT_C 0.1f

// Persistent scratch (no allocations allowed)
__device__ __align__(16) float g_S[2][BB * NN];
__device__ __align__(16) float g_C[2][BB * NN];
__device__ __align__(16) float g_ps[JS][BB * NN];
__device__ __align__(16) float g_pc[JS][BB * NN];
__device__ __align__(16) float g_theta_fallback[BB * NN];

static __device__ __forceinline__ unsigned long long fma2(unsigned long long a,
                                                          unsigned long long b,
                                                          unsigned long long c) {
    unsigned long long d;
    asm("fma.rn.f32x2 %0, %1, %2, %3;" : "=l"(d) : "l"(a), "l"(b), "l"(c));
    return d;
}
static __device__ __forceinline__ float lo2(unsigned long long v) {
    return __uint_as_float((unsigned)(v & 0xffffffffull));
}
static __device__ __forceinline__ float hi2(unsigned long long v) {
    return __uint_as_float((unsigned)(v >> 32));
}

// ---------------- init: copy theta, seed sin/cos (parity 0) ----------------
__global__ void __launch_bounds__(256, 1)
k_init(const float* __restrict__ th_in, float* __restrict__ th_buf) {
    int idx = blockIdx.x * 256 + threadIdx.x;
    float th = th_in[idx];
    th_buf[idx] = th;
    float s, c;
    sincosf(th, &s, &c);
    g_S[0][idx] = s;
    g_C[0][idx] = c;
}

// ---------------- matmul partial: K row-dot with S and C -------------------
// grid = 128 blocks: blockIdx = (ib in 0..15) * 8 + (js in 0..7)
// block = 256 threads: rg = tid>>3 (row group, 4 rows), bg = tid&7 (4 batches)
__global__ void __launch_bounds__(256, 1)
k_matmul(const float* __restrict__ K, int p) {
    int tid = threadIdx.x;
    int rg = tid >> 3;
    int bg = tid & 7;
    int ib = blockIdx.x >> 3;
    int js = blockIdx.x & 7;
    int i_base = ib * ITILE + rg * 4;
    int b_base = bg * 4;
    int j0 = js * JCH;

    const float* __restrict__ Sp = g_S[p];
    const float* __restrict__ Cp = g_C[p];

    unsigned long long as_[4][4], ac_[4][4];
#pragma unroll
    for (int r = 0; r < 4; r++)
#pragma unroll
        for (int b = 0; b < 4; b++) { as_[r][b] = 0ull; ac_[r][b] = 0ull; }

    const float* kbase = K + (size_t)i_base * NN;

#pragma unroll 2
    for (int j = j0; j < j0 + JCH; j += 4) {
        ulonglong2 k2[4], s2[4], c2[4];
#pragma unroll
        for (int r = 0; r < 4; r++)
            k2[r] = *(const ulonglong2*)(kbase + (size_t)r * NN + j);
#pragma unroll
        for (int b = 0; b < 4; b++) {
            s2[b] = *(const ulonglong2*)(Sp + (b_base + b) * NN + j);
            c2[b] = *(const ulonglong2*)(Cp + (b_base + b) * NN + j);
        }
#pragma unroll
        for (int r = 0; r < 4; r++)
#pragma unroll
            for (int b = 0; b < 4; b++) {
                as_[r][b] = fma2(k2[r].x, s2[b].x, as_[r][b]);
                as_[r][b] = fma2(k2[r].y, s2[b].y, as_[r][b]);
                ac_[r][b] = fma2(k2[r].x, c2[b].x, ac_[r][b]);
                ac_[r][b] = fma2(k2[r].y, c2[b].y, ac_[r][b]);
            }
    }

#pragma unroll
    for (int r = 0; r < 4; r++)
#pragma unroll
        for (int b = 0; b < 4; b++) {
            int o = (b_base + b) * NN + i_base + r;
            g_ps[js][o] = lo2(as_[r][b]) + hi2(as_[r][b]);
            g_pc[js][o] = lo2(ac_[r][b]) + hi2(ac_[r][b]);
        }
}

// ---------------- update: reduce partials, integrate, wrap, new sin/cos ----
__global__ void __launch_bounds__(256, 1)
k_update(float* __restrict__ th_io, const float* __restrict__ omega,
         const float* __restrict__ Kg, const float* __restrict__ mu, int p) {
    int idx = blockIdx.x * 256 + threadIdx.x;
    int i = idx & (NN - 1);

    float s = 0.f, c = 0.f;
#pragma unroll
    for (int sp = 0; sp < JS; sp++) {
        s += g_ps[sp][idx];
        c += g_pc[sp][idx];
    }

    float coef = (Kg[0] * (1.0f / NN)) * (mu[0] * 0.5f);
    float th = th_io[idx];
    float si = g_S[p][idx];
    float ci = g_C[p][idx];
    float dth = omega[i] + coef * (ci * s - si * c);
    th = fmaf(DT_C, dth, th);

    float sn, cn;
    sincosf(th, &sn, &cn);
    float w = atan2f(sn, cn);     // wrap to (-pi, pi]
    th_io[idx] = w;

    float sn2, cn2;
    sincosf(w, &sn2, &cn2);       // matches reference: trig of wrapped theta
    g_S[p ^ 1][idx] = sn2;
    g_C[p ^ 1][idx] = cn2;
}

// ---------------- coherence: per-batch mean of sin/cos ---------------------
__global__ void __launch_bounds__(256, 1)
k_coh(float* __restrict__ coh_out, int pfinal) {
    int b = blockIdx.x;
    int tid = threadIdx.x;
    float ss = 0.f, cc = 0.f;
    for (int i = tid; i < NN; i += 256) {
        ss += g_S[pfinal][b * NN + i];
        cc += g_C[pfinal][b * NN + i];
    }
    __shared__ float rs[256], rc[256];
    rs[tid] = ss;
    rc[tid] = cc;
    __syncthreads();
    for (int o = 128; o > 0; o >>= 1) {
        if (tid < o) { rs[tid] += rs[tid + o]; rc[tid] += rc[tid + o]; }
        __syncthreads();
    }
    if (tid == 0) {
        float cm = rc[0] * (1.0f / NN);
        float sm = rs[0] * (1.0f / NN);
        coh_out[b] = sqrtf(cm * cm + sm * sm);
    }
}

extern "C" void kernel_launch(void* const* d_in, const int* in_sizes, int n_in,
                              void* d_out, int out_size) {
    const float* theta = (const float*)d_in[0];
    const float* K     = (const float*)d_in[1];
    const float* omega = (const float*)d_in[2];
    const float* Kg    = (const float*)d_in[3];
    const float* mu    = (const float*)d_in[4];
    float* out = (float*)d_out;

    // Defensive output layout handling: expected [theta(32x2048), coherence(32)]
    float* th_buf;
    float* coh_out = nullptr;
    if (out_size >= BB * NN) {
        th_buf = out;
        if (out_size >= BB * NN + BB) coh_out = out + BB * NN;
    } else {
        // output is coherence-only
        float* sym;
        cudaGetSymbolAddress((void**)&sym, g_theta_fallback);
        th_buf = sym;
        coh_out = out;
    }

    k_init<<<(BB * NN) / 256, 256>>>(theta, th_buf);
    for (int t = 0; t < NSTEPS; t++) {
        int p = t & 1;
        k_matmul<<<16 * JS, 256>>>(K, p);
        k_update<<<(BB * NN) / 256, 256>>>(th_buf, omega, Kg, mu, p);
    }
    if (coh_out) k_coh<<<BB, 256>>>(coh_out, NSTEPS & 1);
}

// round 2
// speedup vs baseline: 9.1848x; 9.1848x over previous
#include <cuda_runtime.h>
#include <cuda_bf16.h>
#include <math.h>

#define NN 2048
#define BB 32
#define NSTEPS 10
#define KSPLIT 8
#define KCH (NN / KSPLIT)     // 256
#define MT 128                // rows per CTA
#define SSTR 264              // smem row stride (elements), pad vs 256
#define SMEM_BYTES ((MT * SSTR + 64 * SSTR) * 2)

// Persistent scratch (no allocations allowed)
__device__ __align__(16) __nv_bfloat16 g_Kb[NN * NN];        // K in bf16 (constant)
__device__ __align__(16) __nv_bfloat16 g_SCb[64 * NN];       // rows 0-31: sin(theta_b), 32-63: cos(theta_b)
__device__ __align__(16) float g_ps[KSPLIT][BB * NN];        // partial K*sin, [b*NN+i]
__device__ __align__(16) float g_pc[KSPLIT][BB * NN];        // partial K*cos
__device__ __align__(16) float g_theta_fallback[BB * NN];

// ---------------- one-time: K fp32 -> bf16 ----------------
__global__ void __launch_bounds__(256, 1)
k_convK(const float* __restrict__ K) {
    int idx = blockIdx.x * 256 + threadIdx.x;     // over NN*NN/4
    float4 v = ((const float4*)K)[idx];
    __nv_bfloat162 lo, hi;
    lo.x = __float2bfloat16(v.x); lo.y = __float2bfloat16(v.y);
    hi.x = __float2bfloat16(v.z); hi.y = __float2bfloat16(v.w);
    ((__nv_bfloat162*)g_Kb)[idx * 2]     = lo;
    ((__nv_bfloat162*)g_Kb)[idx * 2 + 1] = hi;
}

// ---------------- init: copy theta, seed bf16 sin/cos ----------------
__global__ void __launch_bounds__(256, 1)
k_init(const float* __restrict__ th_in, float* __restrict__ th_buf) {
    int idx = blockIdx.x * 256 + threadIdx.x;
    float th = th_in[idx];
    th_buf[idx] = th;
    float s, c;
    sincosf(th, &s, &c);
    g_SCb[idx]           = __float2bfloat16(s);
    g_SCb[32 * NN + idx] = __float2bfloat16(c);
}

// ---------------- GEMM: partial[i, 64cols] += Kb[i, kchunk] * SCb^T ----------
// grid = (KSPLIT, 16), block = 128 (4 warps). Each CTA: 128 rows x 64 cols x 256 k.
// Warp w handles rows [w*32, w*32+32), all 64 cols.
__global__ void __launch_bounds__(128, 1)
k_mma() {
    extern __shared__ __align__(16) char smem_raw[];
    __nv_bfloat16* sA = (__nv_bfloat16*)smem_raw;       // [128][SSTR]
    __nv_bfloat16* sB = sA + MT * SSTR;                 // [64][SSTR]

    int tid  = threadIdx.x;
    int lane = tid & 31;
    int w    = tid >> 5;
    int ks   = blockIdx.x;
    int ib   = blockIdx.y;
    int i0   = ib * MT;
    int k0   = ks * KCH;

    // Load A tile (128 x 256 bf16) and B^T tile (64 x 256 bf16), coalesced 16B
    {
        const __nv_bfloat16* gA = g_Kb + (size_t)i0 * NN + k0;
#pragma unroll
        for (int it = 0; it < MT * (KCH / 8) / 128; it++) {
            int idx = it * 128 + tid;
            int row = idx >> 5;         // KCH/8 = 32 chunks per row
            int ch  = idx & 31;
            *(uint4*)(sA + row * SSTR + ch * 8) =
                *(const uint4*)(gA + (size_t)row * NN + ch * 8);
        }
        const __nv_bfloat16* gB = g_SCb + k0;
#pragma unroll
        for (int it = 0; it < 64 * (KCH / 8) / 128; it++) {
            int idx = it * 128 + tid;
            int row = idx >> 5;
            int ch  = idx & 31;
            *(uint4*)(sB + row * SSTR + ch * 8) =
                *(const uint4*)(gB + (size_t)row * NN + ch * 8);
        }
    }
    __syncthreads();

    float acc[2][8][4];
#pragma unroll
    for (int mt = 0; mt < 2; mt++)
#pragma unroll
        for (int nt = 0; nt < 8; nt++)
#pragma unroll
            for (int r = 0; r < 4; r++) acc[mt][nt][r] = 0.f;

    int g = lane >> 2;      // 0..7
    int t = lane & 3;       // 0..3

    for (int kk = 0; kk < KCH; kk += 16) {
        // B fragments: reg0 = B^T[n][kk+2t .. +1], reg1 = +8 elements
        unsigned bfr[8][2];
#pragma unroll
        for (int nt = 0; nt < 8; nt++) {
            const __nv_bfloat16* p = sB + (nt * 8 + g) * SSTR + kk + 2 * t;
            bfr[nt][0] = *(const unsigned*)p;
            bfr[nt][1] = *(const unsigned*)(p + 8);
        }
#pragma unroll
        for (int mt = 0; mt < 2; mt++) {
            unsigned a0, a1, a2, a3;
            const __nv_bfloat16* ap =
                sA + (w * 32 + mt * 16 + (lane & 15)) * SSTR + kk + ((lane >> 4) * 8);
            unsigned sa = (unsigned)__cvta_generic_to_shared(ap);
            asm volatile(
                "ldmatrix.sync.aligned.m8n8.x4.shared.b16 {%0,%1,%2,%3}, [%4];"
                : "=r"(a0), "=r"(a1), "=r"(a2), "=r"(a3) : "r"(sa));
#pragma unroll
            for (int nt = 0; nt < 8; nt++) {
                asm volatile(
                    "mma.sync.aligned.m16n8k16.row.col.f32.bf16.bf16.f32 "
                    "{%0,%1,%2,%3}, {%4,%5,%6,%7}, {%8,%9}, {%0,%1,%2,%3};"
                    : "+f"(acc[mt][nt][0]), "+f"(acc[mt][nt][1]),
                      "+f"(acc[mt][nt][2]), "+f"(acc[mt][nt][3])
                    : "r"(a0), "r"(a1), "r"(a2), "r"(a3),
                      "r"(bfr[nt][0]), "r"(bfr[nt][1]));
            }
        }
    }

    // Store fp32 partials: cols 0-31 -> g_ps (sin), 32-63 -> g_pc (cos), [col][i]
#pragma unroll
    for (int mt = 0; mt < 2; mt++) {
        int irow = i0 + w * 32 + mt * 16 + g;
#pragma unroll
        for (int nt = 0; nt < 8; nt++) {
            int col = nt * 8 + 2 * t;
            float* dst = (nt < 4) ? g_ps[ks] : g_pc[ks];
            int cb = col & 31;
            dst[(size_t)cb * NN + irow]           = acc[mt][nt][0];
            dst[(size_t)(cb + 1) * NN + irow]     = acc[mt][nt][1];
            dst[(size_t)cb * NN + irow + 8]       = acc[mt][nt][2];
            dst[(size_t)(cb + 1) * NN + irow + 8] = acc[mt][nt][3];
        }
    }
}

// ---------------- update: reduce partials, integrate, wrap, emit bf16 -------
__global__ void __launch_bounds__(256, 1)
k_update(float* __restrict__ th_io, const float* __restrict__ omega,
         const float* __restrict__ Kg, const float* __restrict__ mu) {
    int idx = blockIdx.x * 256 + threadIdx.x;
    int i = idx & (NN - 1);

    float s = 0.f, c = 0.f;
#pragma unroll
    for (int ks = 0; ks < KSPLIT; ks++) {
        s += g_ps[ks][idx];
        c += g_pc[ks][idx];
    }

    float coef = (Kg[0] * (1.0f / NN)) * (mu[0] * 0.5f);
    float th = th_io[idx];
    float si, ci;
    sincosf(th, &si, &ci);
    float dth = omega[i] + coef * (ci * s - si * c);
    th = fmaf(0.1f, dth, th);

    float sn, cn;
    sincosf(th, &sn, &cn);
    float wth = atan2f(sn, cn);          // wrap to (-pi, pi]
    th_io[idx] = wth;

    float s2, c2;
    sincosf(wth, &s2, &c2);              // trig of wrapped theta (matches reference)
    g_SCb[idx]           = __float2bfloat16(s2);
    g_SCb[32 * NN + idx] = __float2bfloat16(c2);
}

// ---------------- coherence ----------------
__global__ void __launch_bounds__(256, 1)
k_coh(const float* __restrict__ th_buf, float* __restrict__ coh_out) {
    int b = blockIdx.x;
    int tid = threadIdx.x;
    float ss = 0.f, cc = 0.f;
    for (int i = tid; i < NN; i += 256) {
        float s, c;
        sincosf(th_buf[b * NN + i], &s, &c);
        ss += s; cc += c;
    }
    __shared__ float rs[256], rc[256];
    rs[tid] = ss; rc[tid] = cc;
    __syncthreads();
    for (int o = 128; o > 0; o >>= 1) {
        if (tid < o) { rs[tid] += rs[tid + o]; rc[tid] += rc[tid + o]; }
        __syncthreads();
    }
    if (tid == 0) {
        float cm = rc[0] * (1.0f / NN);
        float sm = rs[0] * (1.0f / NN);
        coh_out[b] = sqrtf(cm * cm + sm * sm);
    }
}

extern "C" void kernel_launch(void* const* d_in, const int* in_sizes, int n_in,
                              void* d_out, int out_size) {
    const float* theta = (const float*)d_in[0];
    const float* K     = (const float*)d_in[1];
    const float* omega = (const float*)d_in[2];
    const float* Kg    = (const float*)d_in[3];
    const float* mu    = (const float*)d_in[4];
    float* out = (float*)d_out;

    // Output layout: [theta(32x2048), coherence(32)] (verified in R1)
    float* th_buf;
    float* coh_out = nullptr;
    if (out_size >= BB * NN) {
        th_buf = out;
        if (out_size >= BB * NN + BB) coh_out = out + BB * NN;
    } else {
        float* sym;
        cudaGetSymbolAddress((void**)&sym, g_theta_fallback);
        th_buf = sym;
        coh_out = out;
    }

    cudaFuncSetAttribute(k_mma, cudaFuncAttributeMaxDynamicSharedMemorySize,
                         SMEM_BYTES);

    k_convK<<<NN * NN / 1024, 256>>>(K);
    k_init<<<(BB * NN) / 256, 256>>>(theta, th_buf);
    for (int t = 0; t < NSTEPS; t++) {
        k_mma<<<dim3(KSPLIT, NN / MT), 128, SMEM_BYTES>>>();
        k_update<<<(BB * NN) / 256, 256>>>(th_buf, omega, Kg, mu);
    }
    if (coh_out) k_coh<<<BB, 256>>>(th_buf, coh_out);
}

// round 3
// speedup vs baseline: 9.6417x; 1.0497x over previous
#include <cuda_runtime.h>
#include <cuda_bf16.h>
#include <math.h>

#define NN 2048
#define BB 32
#define NSTEPS 10
#define KSPLIT 8
#define KCH (NN / KSPLIT)     // 256
#define MT 128                // rows per CTA
#define SSTR 264              // smem row stride (elements), pad vs 256
#define SMEM_BYTES ((MT * SSTR + 64 * SSTR) * 2)

// Persistent scratch (no allocations allowed)
__device__ __align__(16) __nv_bfloat16 g_Kb[NN * NN];        // K in bf16 (constant)
__device__ __align__(16) __nv_bfloat16 g_SCb[64 * NN];       // rows 0-31: sin(theta_b), 32-63: cos(theta_b)
__device__ __align__(16) float g_ps[KSPLIT][BB * NN];        // partial K*sin, [b*NN+i]
__device__ __align__(16) float g_pc[KSPLIT][BB * NN];        // partial K*cos
__device__ __align__(16) float g_theta_fallback[BB * NN];

// ---------------- one-time: K fp32 -> bf16 ----------------
__global__ void __launch_bounds__(256, 1)
k_convK(const float* __restrict__ K) {
    int idx = blockIdx.x * 256 + threadIdx.x;     // over NN*NN/4
    float4 v = ((const float4*)K)[idx];
    __nv_bfloat162 lo, hi;
    lo.x = __float2bfloat16(v.x); lo.y = __float2bfloat16(v.y);
    hi.x = __float2bfloat16(v.z); hi.y = __float2bfloat16(v.w);
    ((__nv_bfloat162*)g_Kb)[idx * 2]     = lo;
    ((__nv_bfloat162*)g_Kb)[idx * 2 + 1] = hi;
}

// ---------------- init: copy theta, seed bf16 sin/cos ----------------
__global__ void __launch_bounds__(256, 1)
k_init(const float* __restrict__ th_in, float* __restrict__ th_buf) {
    int idx = blockIdx.x * 256 + threadIdx.x;
    float th = th_in[idx];
    th_buf[idx] = th;
    float s, c;
    sincosf(th, &s, &c);       // one-time: accurate
    g_SCb[idx]           = __float2bfloat16(s);
    g_SCb[32 * NN + idx] = __float2bfloat16(c);
}

// ---------------- GEMM: partial[i, 64cols] += Kb[i, kchunk] * SCb^T ----------
// grid = (KSPLIT, 16), block = 128 (4 warps). Each CTA: 128 rows x 64 cols x 256 k.
__global__ void __launch_bounds__(128, 1)
k_mma() {
    extern __shared__ __align__(16) char smem_raw[];
    __nv_bfloat16* sA = (__nv_bfloat16*)smem_raw;       // [128][SSTR]
    __nv_bfloat16* sB = sA + MT * SSTR;                 // [64][SSTR]

    int tid  = threadIdx.x;
    int lane = tid & 31;
    int w    = tid >> 5;
    int ks   = blockIdx.x;
    int ib   = blockIdx.y;
    int i0   = ib * MT;
    int k0   = ks * KCH;

    {
        const __nv_bfloat16* gA = g_Kb + (size_t)i0 * NN + k0;
#pragma unroll
        for (int it = 0; it < MT * (KCH / 8) / 128; it++) {
            int idx = it * 128 + tid;
            int row = idx >> 5;
            int ch  = idx & 31;
            *(uint4*)(sA + row * SSTR + ch * 8) =
                *(const uint4*)(gA + (size_t)row * NN + ch * 8);
        }
        const __nv_bfloat16* gB = g_SCb + k0;
#pragma unroll
        for (int it = 0; it < 64 * (KCH / 8) / 128; it++) {
            int idx = it * 128 + tid;
            int row = idx >> 5;
            int ch  = idx & 31;
            *(uint4*)(sB + row * SSTR + ch * 8) =
                *(const uint4*)(gB + (size_t)row * NN + ch * 8);
        }
    }
    __syncthreads();

    float acc[2][8][4];
#pragma unroll
    for (int mt = 0; mt < 2; mt++)
#pragma unroll
        for (int nt = 0; nt < 8; nt++)
#pragma unroll
            for (int r = 0; r < 4; r++) acc[mt][nt][r] = 0.f;

    int g = lane >> 2;
    int t = lane & 3;

    for (int kk = 0; kk < KCH; kk += 16) {
        unsigned bfr[8][2];
#pragma unroll
        for (int nt = 0; nt < 8; nt++) {
            const __nv_bfloat16* p = sB + (nt * 8 + g) * SSTR + kk + 2 * t;
            bfr[nt][0] = *(const unsigned*)p;
            bfr[nt][1] = *(const unsigned*)(p + 8);
        }
#pragma unroll
        for (int mt = 0; mt < 2; mt++) {
            unsigned a0, a1, a2, a3;
            const __nv_bfloat16* ap =
                sA + (w * 32 + mt * 16 + (lane & 15)) * SSTR + kk + ((lane >> 4) * 8);
            unsigned sa = (unsigned)__cvta_generic_to_shared(ap);
            asm volatile(
                "ldmatrix.sync.aligned.m8n8.x4.shared.b16 {%0,%1,%2,%3}, [%4];"
                : "=r"(a0), "=r"(a1), "=r"(a2), "=r"(a3) : "r"(sa));
#pragma unroll
            for (int nt = 0; nt < 8; nt++) {
                asm volatile(
                    "mma.sync.aligned.m16n8k16.row.col.f32.bf16.bf16.f32 "
                    "{%0,%1,%2,%3}, {%4,%5,%6,%7}, {%8,%9}, {%0,%1,%2,%3};"
                    : "+f"(acc[mt][nt][0]), "+f"(acc[mt][nt][1]),
                      "+f"(acc[mt][nt][2]), "+f"(acc[mt][nt][3])
                    : "r"(a0), "r"(a1), "r"(a2), "r"(a3),
                      "r"(bfr[nt][0]), "r"(bfr[nt][1]));
            }
        }
    }

#pragma unroll
    for (int mt = 0; mt < 2; mt++) {
        int irow = i0 + w * 32 + mt * 16 + g;
#pragma unroll
        for (int nt = 0; nt < 8; nt++) {
            int col = nt * 8 + 2 * t;
            float* dst = (nt < 4) ? g_ps[ks] : g_pc[ks];
            int cb = col & 31;
            dst[(size_t)cb * NN + irow]           = acc[mt][nt][0];
            dst[(size_t)(cb + 1) * NN + irow]     = acc[mt][nt][1];
            dst[(size_t)cb * NN + irow + 8]       = acc[mt][nt][2];
            dst[(size_t)(cb + 1) * NN + irow + 8] = acc[mt][nt][3];
        }
    }
}

// ---------------- update: reduce partials, integrate; wrap only on last -----
// 2 elements/thread, grid = 128 CTAs x 256 thr.
__global__ void __launch_bounds__(256, 1)
k_update(float* __restrict__ th_io, const float* __restrict__ omega,
         const float* __restrict__ Kg, const float* __restrict__ mu, int last) {
    int idx = (blockIdx.x * 256 + threadIdx.x) * 2;
    int i = idx & (NN - 1);

    float2 s = make_float2(0.f, 0.f), c = make_float2(0.f, 0.f);
#pragma unroll
    for (int ks = 0; ks < KSPLIT; ks++) {
        float2 p = *(const float2*)&g_ps[ks][idx];
        s.x += p.x; s.y += p.y;
        p = *(const float2*)&g_pc[ks][idx];
        c.x += p.x; c.y += p.y;
    }

    float coef = (Kg[0] * (1.0f / NN)) * (mu[0] * 0.5f);
    float2 th = *(const float2*)&th_io[idx];
    float2 om = *(const float2*)&omega[i];

    // si, ci: exactly the bf16 values the GEMM consumed (err negligible in dth)
    __nv_bfloat162 sib = *(const __nv_bfloat162*)&g_SCb[idx];
    __nv_bfloat162 cib = *(const __nv_bfloat162*)&g_SCb[32 * NN + idx];
    float2 si = __bfloat1622float2(sib);
    float2 ci = __bfloat1622float2(cib);

    th.x = fmaf(0.1f, om.x + coef * (ci.x * s.x - si.x * c.x), th.x);
    th.y = fmaf(0.1f, om.y + coef * (ci.y * s.y - si.y * c.y), th.y);

    if (last) {
        // reference-exact wrap to (-pi, pi] (done once; intermediate wraps are
        // mathematically transparent to the dynamics)
        float sn, cn;
        sincosf(th.x, &sn, &cn);
        th.x = atan2f(sn, cn);
        sincosf(th.y, &sn, &cn);
        th.y = atan2f(sn, cn);
        *(float2*)&th_io[idx] = th;
    } else {
        *(float2*)&th_io[idx] = th;
        // fast trig for next step's bf16 GEMM operands (bf16 rounding dominates)
        float s0, c0, s1, c1;
        __sincosf(th.x, &s0, &c0);
        __sincosf(th.y, &s1, &c1);
        *(__nv_bfloat162*)&g_SCb[idx]           = __floats2bfloat162_rn(s0, s1);
        *(__nv_bfloat162*)&g_SCb[32 * NN + idx] = __floats2bfloat162_rn(c0, c1);
    }
}

// ---------------- coherence (accurate, from final wrapped theta) ------------
__global__ void __launch_bounds__(256, 1)
k_coh(const float* __restrict__ th_buf, float* __restrict__ coh_out) {
    int b = blockIdx.x;
    int tid = threadIdx.x;
    float ss = 0.f, cc = 0.f;
    for (int i = tid; i < NN; i += 256) {
        float s, c;
        sincosf(th_buf[b * NN + i], &s, &c);
        ss += s; cc += c;
    }
    __shared__ float rs[256], rc[256];
    rs[tid] = ss; rc[tid] = cc;
    __syncthreads();
    for (int o = 128; o > 0; o >>= 1) {
        if (tid < o) { rs[tid] += rs[tid + o]; rc[tid] += rc[tid + o]; }
        __syncthreads();
    }
    if (tid == 0) {
        float cm = rc[0] * (1.0f / NN);
        float sm = rs[0] * (1.0f / NN);
        coh_out[b] = sqrtf(cm * cm + sm * sm);
    }
}

extern "C" void kernel_launch(void* const* d_in, const int* in_sizes, int n_in,
                              void* d_out, int out_size) {
    const float* theta = (const float*)d_in[0];
    const float* K     = (const float*)d_in[1];
    const float* omega = (const float*)d_in[2];
    const float* Kg    = (const float*)d_in[3];
    const float* mu    = (const float*)d_in[4];
    float* out = (float*)d_out;

    float* th_buf;
    float* coh_out = nullptr;
    if (out_size >= BB * NN) {
        th_buf = out;
        if (out_size >= BB * NN + BB) coh_out = out + BB * NN;
    } else {
        float* sym;
        cudaGetSymbolAddress((void**)&sym, g_theta_fallback);
        th_buf = sym;
        coh_out = out;
    }

    cudaFuncSetAttribute(k_mma, cudaFuncAttributeMaxDynamicSharedMemorySize,
                         SMEM_BYTES);

    k_convK<<<NN * NN / 1024, 256>>>(K);
    k_init<<<(BB * NN) / 256, 256>>>(theta, th_buf);
    for (int t = 0; t < NSTEPS; t++) {
        k_mma<<<dim3(KSPLIT, NN / MT), 128, SMEM_BYTES>>>();
        k_update<<<(BB * NN) / 512, 256>>>(th_buf, omega, Kg, mu,
                                           t == NSTEPS - 1);
    }
    if (coh_out) k_coh<<<BB, 256>>>(th_buf, coh_out);
}